// round 6
// baseline (speedup 1.0000x reference)
#include <cuda_runtime.h>
#include <stdint.h>

// GraphRewiring: transitive closure of body-edge adjacency (attr==0),
// emit shortcut edges (closure & ~adj) appended to original edge list.
//
// R6 (= R5 re-bench; container died before running R5): frontier (delta)
// expansion, fused persistent kernel.
//   - convergence flag: block-aggregated (smem) -> <=128 global stores/reads
//     per iteration instead of 64K same-address L2 hits
//   - dense delta words (popc>=12): streaming gather (no ffs chains, no votes)
//   - phase 3 emit spread over the full 64K-thread grid
//
// Output layout (float32, out_size = 3*(E+N*N)):
//   [0, E)               : edge_index[0] (src) as float
//   [E, E+NN)            : new_src
//   [E+NN, 2E+NN)        : edge_index[1] (dst) as float
//   [2E+NN, 2E+2NN)      : new_dst
//   [2(E+NN), 2(E+NN)+E) : edge_attr copy
//   [2(E+NN)+E, 3(E+NN)) : new_attr (3.0 if shortcut else -1.0)

#define N_NODES 1024
#define NW 32
#define FULLMASK 0xFFFFFFFFu
#define GRID 128
#define TPB 512
#define MAX_ITERS 12
#define NBAR 16

static __device__ uint32_t g_adj[N_NODES * NW];
static __device__ uint32_t g_R[N_NODES * NW];
static __device__ int g_i64flag;
static __device__ int g_bar[NBAR];          // monotone arrival counters
static __device__ int g_changed[MAX_ITERS];

// ---------------------------------------------------------------------------
__global__ void init_kernel(const int* __restrict__ ei32) {
    int t = blockIdx.x * blockDim.x + threadIdx.x;
    if (t < N_NODES * NW) { g_adj[t] = 0u; g_R[t] = 0u; }
    if (t < NBAR) g_bar[t] = 0;
    if (t < MAX_ITERS) g_changed[t] = 0;
    if (t == 0) {
        // int64 little-endian with node ids < 1024 => every odd word is 0.
        int allzero = 1;
        for (int k = 0; k < 64; k++)
            if (ei32[2 * k + 1] != 0) { allzero = 0; break; }
        g_i64flag = allzero;
    }
}

// ---------------------------------------------------------------------------
// Grid barrier + per-iteration flag exchange. 128 blocks x 512 threads at
// 1 block/SM (launch_bounds) on 148 SMs => all co-resident, spin is
// deadlock-free. Thread 0: publish block's changed bit (<=128 single-address
// stores grid-wide), release fence, arrive, spin, acquire fence, read the
// global flag once (<=128 reads grid-wide), broadcast via smem.
__device__ __forceinline__ int grid_sync_flag(int slot, int it,
                                              int* s_changed, int* s_flag) {
    __syncthreads();
    if (threadIdx.x == 0) {
        if (it >= 0 && *s_changed) g_changed[it] = 1;
        *s_changed = 0;
        __threadfence();
        atomicAdd(&g_bar[slot], 1);
        while (*(volatile int*)&g_bar[slot] < GRID) __nanosleep(32);
        __threadfence();
        *s_flag = (it >= 0) ? __ldcg(&g_changed[it]) : 1;
    }
    __syncthreads();
    return *s_flag;
}

// ---------------------------------------------------------------------------
__global__ void __launch_bounds__(TPB, 1)
fused_kernel(const int* __restrict__ ei32, const float* __restrict__ attr,
             float* __restrict__ out, int E) {
    __shared__ int s_changed, s_flag;
    const int tid  = blockIdx.x * TPB + threadIdx.x;   // 0..65535
    const int lane = threadIdx.x & 31;
    const int warp = tid >> 5;                         // 0..2047
    const int row  = warp >> 1;                        // 2 warps per row
    const int kwlo = (warp & 1) << 4;                  // kw range [kwlo,kwlo+16)
    const int i64  = g_i64flag;
    const int NN   = N_NODES * N_NODES;
    int bar = 0;

    if (threadIdx.x == 0) { s_changed = 0; s_flag = 1; }

    // ---- Phase 1: copy originals + build body-edge adjacency bitsets ------
    for (int e = tid; e < E; e += GRID * TPB) {
        int src, dst;
        if (i64) { src = ei32[2 * e]; dst = ei32[2 * (E + e)]; }
        else     { src = ei32[e];     dst = ei32[E + e]; }
        float a = attr[e];
        out[e] = (float)src;
        out[(E + NN) + e] = (float)dst;
        out[2 * (E + NN) + e] = a;
        if (a == 0.0f) {
            uint32_t m = 1u << (dst & 31);
            int idx = src * NW + (dst >> 5);
            atomicOr(&g_adj[idx], m);
            atomicOr(&g_R[idx], m);
        }
    }
    grid_sync_flag(bar++, -1, &s_changed, &s_flag);

    // ---- Phase 2: frontier expansion until fixpoint ------------------------
    uint32_t rowreg   = __ldcg(&g_R[row * NW + lane]);
    uint32_t expanded = 0;   // bits already expanded by this warp

    for (int it = 0; it < MAX_ITERS; it++) {
        uint32_t delta = rowreg & ~expanded;
        uint32_t acc = rowreg;

        if (__any_sync(FULLMASK, delta != 0u)) {
            #pragma unroll 1
            for (int kw = kwlo; kw < kwlo + 16; kw++) {
                uint32_t bits = __shfl_sync(FULLMASK, delta, kw);  // warp-uniform
                if (!bits) continue;
                const uint32_t* pk = &g_R[(kw << 10) + lane];      // k=kw*32+j
                if (__popc(bits) >= 12) {
                    // Streaming: load all 32 rows of this word, predicated OR.
                    // No serial ffs chain; 8 loads in flight per group.
                    #pragma unroll
                    for (int j = 0; j < 32; j += 8) {
                        uint32_t v0 = pk[(j + 0) << 5];
                        uint32_t v1 = pk[(j + 1) << 5];
                        uint32_t v2 = pk[(j + 2) << 5];
                        uint32_t v3 = pk[(j + 3) << 5];
                        uint32_t v4 = pk[(j + 4) << 5];
                        uint32_t v5 = pk[(j + 5) << 5];
                        uint32_t v6 = pk[(j + 6) << 5];
                        uint32_t v7 = pk[(j + 7) << 5];
                        if (bits & (1u << (j + 0))) acc |= v0;
                        if (bits & (1u << (j + 1))) acc |= v1;
                        if (bits & (1u << (j + 2))) acc |= v2;
                        if (bits & (1u << (j + 3))) acc |= v3;
                        if (bits & (1u << (j + 4))) acc |= v4;
                        if (bits & (1u << (j + 5))) acc |= v5;
                        if (bits & (1u << (j + 6))) acc |= v6;
                        if (bits & (1u << (j + 7))) acc |= v7;
                    }
                } else {
                    // Sparse: ffs batches of 8 (MLP=8), no per-batch votes.
                    while (bits) {
                        int j0_ = __ffs(bits) - 1; bits &= bits - 1;
                        int j1_ = j0_, j2_ = j0_, j3_ = j0_;
                        int j4_ = j0_, j5_ = j0_, j6_ = j0_, j7_ = j0_;
                        if (bits) { j1_ = __ffs(bits) - 1; bits &= bits - 1; }
                        if (bits) { j2_ = __ffs(bits) - 1; bits &= bits - 1; }
                        if (bits) { j3_ = __ffs(bits) - 1; bits &= bits - 1; }
                        if (bits) { j4_ = __ffs(bits) - 1; bits &= bits - 1; }
                        if (bits) { j5_ = __ffs(bits) - 1; bits &= bits - 1; }
                        if (bits) { j6_ = __ffs(bits) - 1; bits &= bits - 1; }
                        if (bits) { j7_ = __ffs(bits) - 1; bits &= bits - 1; }
                        uint32_t v0 = pk[j0_ << 5];
                        uint32_t v1 = pk[j1_ << 5];
                        uint32_t v2 = pk[j2_ << 5];
                        uint32_t v3 = pk[j3_ << 5];
                        uint32_t v4 = pk[j4_ << 5];
                        uint32_t v5 = pk[j5_ << 5];
                        uint32_t v6 = pk[j6_ << 5];
                        uint32_t v7 = pk[j7_ << 5];
                        acc |= (v0 | v1) | (v2 | v3) | (v4 | v5) | (v6 | v7);
                    }
                }
            }
        }

        expanded = rowreg;                   // every pre-pass bit now expanded
        uint32_t newbits = acc & ~rowreg;
        if (__any_sync(FULLMASK, newbits != 0u)) {
            if (newbits) atomicOr(&g_R[row * NW + lane], newbits);
            if (lane == 0) s_changed = 1;    // smem aggregate, not global
        }
        int flag = grid_sync_flag(bar++, it, &s_changed, &s_flag);
        rowreg = __ldcg(&g_R[row * NW + lane]);  // fresh merged row
        if (flag == 0) break;                    // grid-uniform fixpoint
    }

    // ---- Phase 3: emit shortcut slots (closure & ~adj), full grid ----------
    {
        int t = tid >> 1;                    // word 0..32767
        int half = tid & 1;                  // 16 slots per thread
        uint32_t sc = (__ldcg(&g_R[t]) & ~g_adj[t]) >> (half << 4);
        int p_base = (t << 5) + (half << 4);
        int j0 = ((t & 31) << 5) + (half << 4);
        float fi = (float)(t >> 5);

        float* so = out + E + p_base;                   // new_src
        float* dd = out + (E + NN) + E + p_base;        // new_dst
        float* ao = out + 2 * (E + NN) + E + p_base;    // new_attr

        #pragma unroll
        for (int q = 0; q < 16; q += 4) {
            bool b0 = (sc >> (q + 0)) & 1u;
            bool b1 = (sc >> (q + 1)) & 1u;
            bool b2 = (sc >> (q + 2)) & 1u;
            bool b3 = (sc >> (q + 3)) & 1u;
            float4 s4 = make_float4(b0 ? fi : 0.f, b1 ? fi : 0.f,
                                    b2 ? fi : 0.f, b3 ? fi : 0.f);
            float4 d4 = make_float4(b0 ? (float)(j0 + q + 0) : 0.f,
                                    b1 ? (float)(j0 + q + 1) : 0.f,
                                    b2 ? (float)(j0 + q + 2) : 0.f,
                                    b3 ? (float)(j0 + q + 3) : 0.f);
            float4 a4 = make_float4(b0 ? 3.f : -1.f, b1 ? 3.f : -1.f,
                                    b2 ? 3.f : -1.f, b3 ? 3.f : -1.f);
            *(float4*)(so + q) = s4;
            *(float4*)(dd + q) = d4;
            *(float4*)(ao + q) = a4;
        }
    }
}

// ---------------------------------------------------------------------------
extern "C" void kernel_launch(void* const* d_in, const int* in_sizes, int n_in,
                              void* d_out, int out_size) {
    const int* ei = (const int*)d_in[0];
    const float* attr = (const float*)d_in[1];
    float* out = (float*)d_out;
    int E = in_sizes[1];

    init_kernel<<<64, 512>>>(ei);
    fused_kernel<<<GRID, TPB>>>(ei, attr, out, E);
}

// round 7
// speedup vs baseline: 1.6375x; 1.6375x over previous
#include <cuda_runtime.h>
#include <stdint.h>

// GraphRewiring: transitive closure of body-edge adjacency (attr==0),
// emit shortcut edges (closure & ~adj) appended to original edge list.
//
// R7: SCC warm-start + per-phase kernels (for ncu attribution).
//   A init    : zero scratch, detect int64-vs-int32, find pivot
//   B build   : copy originals, scatter adj + reverse-adj bitsets
//   C bfs     : block 0 forward BFS from pivot -> F = closure(pivot)
//               block 1 backward BFS          -> B = {i : i reaches pivot}
//   D expand  : seed R[i] = adj | (i in B ? F|{p} : 0), pre-mark F&B as
//               expanded (closure(k)==F for k in F&B), then generic frontier
//               expansion to fixpoint (fallback; expected ~zero work)
//   E emit    : shortcut slots (closure & ~adj) + layout
//
// Output layout (float32, out_size = 3*(E+N*N)):
//   [0, E)               : edge_index[0] (src) as float
//   [E, E+NN)            : new_src
//   [E+NN, 2E+NN)        : edge_index[1] (dst) as float
//   [2E+NN, 2E+2NN)      : new_dst
//   [2(E+NN), 2(E+NN)+E) : edge_attr copy
//   [2(E+NN)+E, 3(E+NN)) : new_attr (3.0 if shortcut else -1.0)

#define N_NODES 1024
#define NW 32
#define FULLMASK 0xFFFFFFFFu
#define GRID_D 64
#define TPB 512
#define MAX_ITERS 12
#define NBAR 16

static __device__ uint32_t g_adj[N_NODES * NW];
static __device__ uint32_t g_radj[N_NODES * NW];
static __device__ uint32_t g_R[N_NODES * NW];
static __device__ uint32_t g_F[NW];
static __device__ uint32_t g_B[NW];
static __device__ int g_pivot;
static __device__ int g_i64flag;
static __device__ int g_bar[NBAR];
static __device__ int g_changed[MAX_ITERS];

// ---------------------------------------------------------------------------
// A: zero scratch, detect dtype, pick pivot = dst of first body edge.
__global__ void init_kernel(const int* __restrict__ ei32,
                            const float* __restrict__ attr, int E) {
    int t = blockIdx.x * blockDim.x + threadIdx.x;
    if (t < N_NODES * NW) { g_adj[t] = 0u; g_radj[t] = 0u; }
    if (t < NBAR) g_bar[t] = 0;
    if (t < MAX_ITERS) g_changed[t] = 0;
    if (t == 0) {
        // int64 little-endian with node ids < 1024 => every odd word is 0.
        int allzero = 1;
        for (int k = 0; k < 64; k++)
            if (ei32[2 * k + 1] != 0) { allzero = 0; break; }
        g_i64flag = allzero;
        // pivot = dst of first body edge (has in-degree >= 1)
        int p = 0;
        for (int e = 0; e < E; e++) {
            if (attr[e] == 0.0f) {
                p = allzero ? ei32[2 * (E + e)] : ei32[E + e];
                break;
            }
        }
        g_pivot = p;
    }
}

// ---------------------------------------------------------------------------
// B: copy originals, scatter body edges into adj and reverse-adj bitsets.
__global__ void build_kernel(const int* __restrict__ ei32,
                             const float* __restrict__ attr,
                             float* __restrict__ out, int E) {
    const int NN = N_NODES * N_NODES;
    int e = blockIdx.x * blockDim.x + threadIdx.x;
    if (e >= E) return;
    int src, dst;
    if (g_i64flag) { src = ei32[2 * e]; dst = ei32[2 * (E + e)]; }
    else           { src = ei32[e];     dst = ei32[E + e]; }
    float a = attr[e];
    out[e] = (float)src;
    out[(E + NN) + e] = (float)dst;
    out[2 * (E + NN) + e] = a;
    if (a == 0.0f) {
        atomicOr(&g_adj[src * NW + (dst >> 5)], 1u << (dst & 31));
        atomicOr(&g_radj[dst * NW + (src >> 5)], 1u << (src & 31));
    }
}

// ---------------------------------------------------------------------------
// C: single-row BFS to exact fixpoint. block 0: forward (g_adj) -> g_F.
//    block 1: backward (g_radj) -> g_B. Closure = paths of length >= 1, so
//    the seed is the pivot's adjacency row (not the pivot bit).
__global__ void __launch_bounds__(TPB, 1) bfs_kernel() {
    __shared__ uint32_t sR[NW], sExp[NW], sFr[NW];
    __shared__ int sAny;
    const uint32_t* Adj = (blockIdx.x == 0) ? g_adj : g_radj;
    const int tid  = threadIdx.x;
    const int wid  = tid >> 5;
    const int lane = tid & 31;
    const int p = g_pivot;

    if (tid < NW) { sR[tid] = Adj[p * NW + tid]; sExp[tid] = 0u; }
    __syncthreads();

    for (int level = 0; level < N_NODES + 1; level++) {
        if (tid == 0) sAny = 0;
        __syncthreads();
        if (tid < NW) {
            sFr[tid] = sR[tid] & ~sExp[tid];
            sExp[tid] = sR[tid];
            if (sFr[tid]) sAny = 1;      // benign race, all write 1
        }
        __syncthreads();
        if (!sAny) break;

        // 16 warps; warp w expands frontier words w and w+16.
        uint32_t accum = 0;
        #pragma unroll 1
        for (int ww = wid; ww < NW; ww += 16) {
            uint32_t bits = sFr[ww];     // warp-uniform (smem broadcast)
            const uint32_t* pk = &Adj[(ww << 10) + lane];
            while (bits) {
                int j0 = __ffs(bits) - 1; bits &= bits - 1;
                int j1 = j0, j2 = j0, j3 = j0;
                if (bits) { j1 = __ffs(bits) - 1; bits &= bits - 1; }
                if (bits) { j2 = __ffs(bits) - 1; bits &= bits - 1; }
                if (bits) { j3 = __ffs(bits) - 1; bits &= bits - 1; }
                accum |= pk[j0 << 5] | pk[j1 << 5] | pk[j2 << 5] | pk[j3 << 5];
            }
        }
        if (accum) atomicOr(&sR[lane], accum);
        __syncthreads();
    }

    if (tid < NW) {
        if (blockIdx.x == 0) g_F[tid] = sR[tid];
        else                 g_B[tid] = sR[tid];
    }
}

// ---------------------------------------------------------------------------
// Grid barrier + flag exchange for kernel D. 64 blocks x 512 thr at
// 1 block/SM => co-resident, spin deadlock-free.
__device__ __forceinline__ int grid_sync_flag(int slot, int it,
                                              int* s_changed, int* s_flag) {
    __syncthreads();
    if (threadIdx.x == 0) {
        if (it >= 0 && *s_changed) g_changed[it] = 1;
        *s_changed = 0;
        __threadfence();
        atomicAdd(&g_bar[slot], 1);
        while (*(volatile int*)&g_bar[slot] < GRID_D) __nanosleep(32);
        __threadfence();
        *s_flag = (it >= 0) ? __ldcg(&g_changed[it]) : 1;
    }
    __syncthreads();
    return *s_flag;
}

// ---------------------------------------------------------------------------
// D: seed rows with warm start, then frontier expansion to fixpoint.
// 64 blocks x 512 threads = 1024 warps = 1 warp per row.
__global__ void __launch_bounds__(TPB, 1)
expand_kernel() {
    __shared__ int s_changed, s_flag;
    const int tid  = blockIdx.x * TPB + threadIdx.x;
    const int lane = threadIdx.x & 31;
    const int row  = tid >> 5;                 // 0..1023
    int bar = 0;

    if (threadIdx.x == 0) { s_changed = 0; s_flag = 1; }

    const int p = g_pivot;
    const uint32_t Fl = g_F[lane];
    const uint32_t Bl = g_B[lane];
    const int inB = (g_B[row >> 5] >> (row & 31)) & 1;

    uint32_t rowreg = g_adj[(row << 5) + lane];
    uint32_t expanded = 0;
    if (inB) {
        // closure(row) >= F u {p}; closure(k) == F exactly for k in F&B.
        rowreg |= Fl;
        if (lane == (p >> 5)) rowreg |= 1u << (p & 31);
        expanded = Fl & Bl;
    }
    g_R[(row << 5) + lane] = rowreg;
    grid_sync_flag(bar++, -1, &s_changed, &s_flag);

    for (int it = 0; it < MAX_ITERS; it++) {
        uint32_t delta = rowreg & ~expanded;
        uint32_t acc = rowreg;

        if (__any_sync(FULLMASK, delta != 0u)) {
            #pragma unroll 1
            for (int kw = 0; kw < NW; kw++) {
                uint32_t bits = __shfl_sync(FULLMASK, delta, kw);
                if (!bits) continue;
                const uint32_t* pk = &g_R[(kw << 10) + lane];
                while (bits) {
                    int j0 = __ffs(bits) - 1; bits &= bits - 1;
                    int j1 = j0, j2 = j0, j3 = j0;
                    int j4 = j0, j5 = j0, j6 = j0, j7 = j0;
                    if (bits) { j1 = __ffs(bits) - 1; bits &= bits - 1; }
                    if (bits) { j2 = __ffs(bits) - 1; bits &= bits - 1; }
                    if (bits) { j3 = __ffs(bits) - 1; bits &= bits - 1; }
                    if (bits) { j4 = __ffs(bits) - 1; bits &= bits - 1; }
                    if (bits) { j5 = __ffs(bits) - 1; bits &= bits - 1; }
                    if (bits) { j6 = __ffs(bits) - 1; bits &= bits - 1; }
                    if (bits) { j7 = __ffs(bits) - 1; bits &= bits - 1; }
                    uint32_t v0 = pk[j0 << 5];
                    uint32_t v1 = pk[j1 << 5];
                    uint32_t v2 = pk[j2 << 5];
                    uint32_t v3 = pk[j3 << 5];
                    uint32_t v4 = pk[j4 << 5];
                    uint32_t v5 = pk[j5 << 5];
                    uint32_t v6 = pk[j6 << 5];
                    uint32_t v7 = pk[j7 << 5];
                    acc |= (v0 | v1) | (v2 | v3) | (v4 | v5) | (v6 | v7);
                }
            }
        }

        expanded = rowreg;
        uint32_t newbits = acc & ~rowreg;
        if (__any_sync(FULLMASK, newbits != 0u)) {
            if (newbits) atomicOr(&g_R[(row << 5) + lane], newbits);
            if (lane == 0) s_changed = 1;
        }
        int flag = grid_sync_flag(bar++, it, &s_changed, &s_flag);
        rowreg = __ldcg(&g_R[(row << 5) + lane]);
        if (flag == 0) break;
    }
}

// ---------------------------------------------------------------------------
// E: emit shortcut slots. 64K threads, 16 slots (half a word) per thread.
__global__ void emit_kernel(float* __restrict__ out, int E) {
    const int NN = N_NODES * N_NODES;
    int tid = blockIdx.x * blockDim.x + threadIdx.x;   // 0..65535
    int t = tid >> 1;
    int half = tid & 1;
    uint32_t sc = (g_R[t] & ~g_adj[t]) >> (half << 4);
    int p_base = (t << 5) + (half << 4);
    int j0 = ((t & 31) << 5) + (half << 4);
    float fi = (float)(t >> 5);

    float* so = out + E + p_base;                   // new_src
    float* dd = out + (E + NN) + E + p_base;        // new_dst
    float* ao = out + 2 * (E + NN) + E + p_base;    // new_attr

    #pragma unroll
    for (int q = 0; q < 16; q += 4) {
        bool b0 = (sc >> (q + 0)) & 1u;
        bool b1 = (sc >> (q + 1)) & 1u;
        bool b2 = (sc >> (q + 2)) & 1u;
        bool b3 = (sc >> (q + 3)) & 1u;
        float4 s4 = make_float4(b0 ? fi : 0.f, b1 ? fi : 0.f,
                                b2 ? fi : 0.f, b3 ? fi : 0.f);
        float4 d4 = make_float4(b0 ? (float)(j0 + q + 0) : 0.f,
                                b1 ? (float)(j0 + q + 1) : 0.f,
                                b2 ? (float)(j0 + q + 2) : 0.f,
                                b3 ? (float)(j0 + q + 3) : 0.f);
        float4 a4 = make_float4(b0 ? 3.f : -1.f, b1 ? 3.f : -1.f,
                                b2 ? 3.f : -1.f, b3 ? 3.f : -1.f);
        *(float4*)(so + q) = s4;
        *(float4*)(dd + q) = d4;
        *(float4*)(ao + q) = a4;
    }
}

// ---------------------------------------------------------------------------
extern "C" void kernel_launch(void* const* d_in, const int* in_sizes, int n_in,
                              void* d_out, int out_size) {
    const int* ei = (const int*)d_in[0];
    const float* attr = (const float*)d_in[1];
    float* out = (float*)d_out;
    int E = in_sizes[1];

    init_kernel<<<64, 512>>>(ei, attr, E);
    build_kernel<<<(E + 255) / 256, 256>>>(ei, attr, out, E);
    bfs_kernel<<<2, TPB>>>();
    expand_kernel<<<GRID_D, TPB>>>();
    emit_kernel<<<128, 512>>>(out, E);
}